// round 1
// baseline (speedup 1.0000x reference)
#include <cuda_runtime.h>
#include <cstdint>

// Problem dims (fixed): x (4,2048,4096) f32, kernel (4096,16384) f32, bias (16384)
// out (4,2048,16384) f32
#define M_TOK   8192      // 4*2048 tokens
#define D_DIM   4096
#define F_DIM   16384
#define NCHUNK  128       // 4096 / 32 sign bits per u32
#define F32_EPS 1.1920929e-07f

// Scratch (static device globals; no runtime allocation)
__device__ __align__(16) uint32_t g_Xbits[NCHUNK * M_TOK];   // [chunk][token]  4 MB
__device__ __align__(16) uint32_t g_Kbits[NCHUNK * F_DIM];   // [chunk][feature] 8 MB
__device__ float g_bx[M_TOK];
__device__ float g_bkpart[16][F_DIM];
__device__ float g_bk[F_DIM];

// ---------------------------------------------------------------------------
// Pass A: per-token max|x| and sign-bit pack. One warp per token; lane reads
// x[token][c*32+lane] (coalesced), ballot packs the 32 sign bits.
// ---------------------------------------------------------------------------
__global__ void pack_x_kernel(const float* __restrict__ x) {
    int token = blockIdx.x * (blockDim.x >> 5) + (threadIdx.x >> 5);
    int lane  = threadIdx.x & 31;
    const float* row = x + (size_t)token * D_DIM;
    float m = 0.f;
    #pragma unroll 4
    for (int c = 0; c < NCHUNK; ++c) {
        float v = row[c * 32 + lane];
        m = fmaxf(m, fabsf(v));
        unsigned w = __ballot_sync(0xffffffffu, v < 0.f);
        if (lane == 0) g_Xbits[c * M_TOK + token] = w;
    }
    #pragma unroll
    for (int o = 16; o; o >>= 1) m = fmaxf(m, __shfl_xor_sync(0xffffffffu, m, o));
    if (lane == 0) g_bx[token] = m + F32_EPS;
}

// ---------------------------------------------------------------------------
// Pass B: per-feature (column) partial max + sign-bit pack. Thread = feature,
// loads coalesced across features; D split into 16 segments of 8 chunks for
// parallelism. Bit i of chunk c = sign(K[(c*32+i)][f]).
// ---------------------------------------------------------------------------
__global__ void pack_k_kernel(const float* __restrict__ kern) {
    int f   = blockIdx.x * blockDim.x + threadIdx.x;   // gridDim.x = F/256
    int seg = blockIdx.y;                              // 16 segments
    int c0  = seg * 8;
    float m = 0.f;
    for (int c = 0; c < 8; ++c) {
        const float* p = kern + (size_t)((c0 + c) * 32) * F_DIM + f;
        unsigned w = 0;
        #pragma unroll
        for (int i = 0; i < 32; ++i) {
            float v = p[(size_t)i * F_DIM];
            m = fmaxf(m, fabsf(v));
            w |= (v < 0.f ? 1u : 0u) << i;
        }
        g_Kbits[(c0 + c) * F_DIM + f] = w;
    }
    g_bkpart[seg][f] = m;
}

__global__ void reduce_bk_kernel() {
    int f = blockIdx.x * blockDim.x + threadIdx.x;
    float m = 0.f;
    #pragma unroll
    for (int s = 0; s < 16; ++s) m = fmaxf(m, g_bkpart[s][f]);
    g_bk[f] = m + F32_EPS;
}

// ---------------------------------------------------------------------------
// Pass C: XNOR-popcount GEMM. Block tile 128x128, 256 threads, 8x8 per thread.
// Smem tiles chunk-major so operand reads are row-contiguous uint4 LDS.128
// (X reads broadcast within warp; K reads at worst 2-way conflicted).
// dot = D - 2*popcount(xor);  y = 0.25*bx*bk*dot + bias
// ---------------------------------------------------------------------------
#define BM 128
#define BN 128
#define CK 16

__global__ __launch_bounds__(256, 2)
void bgemm_kernel(const float* __restrict__ bias, float* __restrict__ out) {
    __shared__ __align__(16) uint32_t Xs[CK][BM];
    __shared__ __align__(16) uint32_t Ks[CK][BN];

    const int t  = threadIdx.x;
    const int w  = t >> 5, l = t & 31;
    const int wr = w & 3,  wc = w >> 2;   // warps: 4 (rows) x 2 (cols)
    const int lr = l >> 3, lc = l & 7;    // lanes: 4 x 8
    const int row0 = wr * 32 + lr * 8;    // tile-local row of 8x8 patch
    const int col0 = wc * 64 + lc * 8;
    const int t0 = blockIdx.y * BM;       // token base (64 tiles)
    const int f0 = blockIdx.x * BN;       // feature base (128 tiles)

    int acc[8][8];
    #pragma unroll
    for (int i = 0; i < 8; ++i)
        #pragma unroll
        for (int j = 0; j < 8; ++j) acc[i][j] = 0;

    for (int k0 = 0; k0 < NCHUNK; k0 += CK) {
        // Load tiles: CK k-slices x 128 contiguous tokens/features each.
        #pragma unroll
        for (int r = t; r < CK * 32; r += 256) {
            int k = r >> 5, q = (r & 31) << 2;
            *(uint4*)&Xs[k][q] =
                *(const uint4*)&g_Xbits[(size_t)(k0 + k) * M_TOK + t0 + q];
        }
        #pragma unroll
        for (int r = t; r < CK * 32; r += 256) {
            int k = r >> 5, q = (r & 31) << 2;
            *(uint4*)&Ks[k][q] =
                *(const uint4*)&g_Kbits[(size_t)(k0 + k) * F_DIM + f0 + q];
        }
        __syncthreads();

        #pragma unroll
        for (int k = 0; k < CK; ++k) {
            uint32_t xa[8], kb[8];
            *(uint4*)&xa[0] = *(const uint4*)&Xs[k][row0];
            *(uint4*)&xa[4] = *(const uint4*)&Xs[k][row0 + 4];
            *(uint4*)&kb[0] = *(const uint4*)&Ks[k][col0];
            *(uint4*)&kb[4] = *(const uint4*)&Ks[k][col0 + 4];
            #pragma unroll
            for (int i = 0; i < 8; ++i)
                #pragma unroll
                for (int j = 0; j < 8; ++j)
                    acc[i][j] += __popc(xa[i] ^ kb[j]);
        }
        __syncthreads();
    }

    // Epilogue
    const int trow = t0 + row0;
    const int tcol = f0 + col0;
    float bx4[8], bk4[8], bsv[8];
    #pragma unroll
    for (int i = 0; i < 8; ++i) bx4[i] = 0.25f * g_bx[trow + i];
    #pragma unroll
    for (int j = 0; j < 8; ++j) bk4[j] = g_bk[tcol + j];
    #pragma unroll
    for (int j = 0; j < 8; ++j) bsv[j] = bias[tcol + j];

    #pragma unroll
    for (int i = 0; i < 8; ++i) {
        float r[8];
        #pragma unroll
        for (int j = 0; j < 8; ++j) {
            float dot = (float)(D_DIM - 2 * acc[i][j]);
            r[j] = fmaf(bx4[i] * bk4[j], dot, bsv[j]);
        }
        float* po = out + (size_t)(trow + i) * F_DIM + tcol;
        *(float4*)(po)     = make_float4(r[0], r[1], r[2], r[3]);
        *(float4*)(po + 4) = make_float4(r[4], r[5], r[6], r[7]);
    }
}

// ---------------------------------------------------------------------------
extern "C" void kernel_launch(void* const* d_in, const int* in_sizes, int n_in,
                              void* d_out, int out_size) {
    const float* x    = (const float*)d_in[0];
    const float* kern = (const float*)d_in[1];
    const float* bias = (const float*)d_in[2];
    float* out = (float*)d_out;

    // Pass A: 8192 tokens, 8 warps/block
    pack_x_kernel<<<M_TOK / 8, 256>>>(x);

    // Pass B: features x 16 D-segments
    dim3 gb(F_DIM / 256, 16);
    pack_k_kernel<<<gb, 256>>>(kern);
    reduce_bk_kernel<<<F_DIM / 256, 256>>>();

    // Pass C: 128 feature tiles x 64 token tiles
    dim3 gc(F_DIM / BN, M_TOK / BM);
    bgemm_kernel<<<gc, 256>>>(bias, out);
}